// round 2
// baseline (speedup 1.0000x reference)
#include <cuda_runtime.h>
#include <cuda_bf16.h>
#include <math.h>

#define NP 100000
#define ND 50000
#define DIM 128
#define NE 600000
#define ROWS_PER_BLK 8

// ---------------- scratch (static device globals; no allocation allowed) ----
__device__ int   g_deg_pd_src[NP];   // out-degree of p in p->d graph
__device__ int   g_deg_pd_dst[ND];   // in-degree of d in p->d graph
__device__ int   g_deg_dp_src[ND];   // out-degree of d in d->p graph
__device__ int   g_deg_dp_dst[NP];   // in-degree of p in d->p graph
__device__ float g_rs_pd_src[NP];
__device__ float g_rs_pd_dst[ND];
__device__ float g_rs_dp_src[ND];
__device__ float g_rs_dp_dst[NP];
__device__ int   g_off_pd[ND + 1];
__device__ int   g_off_dp[NP + 1];
__device__ int   g_cur_pd[ND];
__device__ int   g_cur_dp[NP];
__device__ int   g_idx_pd[NE];
__device__ int   g_idx_dp[NE];
__device__ int   g_bsums_pd[256];
__device__ int   g_bsums_dp[256];
__device__ float g_hd1[(size_t)ND * DIM];
__device__ float g_hd2[(size_t)ND * DIM];
__device__ float g_hp1[(size_t)NP * DIM];
__device__ float g_hp2[(size_t)NP * DIM];

// ---------------- degree histogram ----------------
__global__ void hist_kernel(const int* __restrict__ pd_src, const int* __restrict__ pd_dst,
                            const int* __restrict__ dp_src, const int* __restrict__ dp_dst) {
    int i = blockIdx.x * blockDim.x + threadIdx.x;
    if (i < NE) {
        atomicAdd(&g_deg_pd_src[pd_src[i]], 1);
        atomicAdd(&g_deg_pd_dst[pd_dst[i]], 1);
        atomicAdd(&g_deg_dp_src[dp_src[i]], 1);
        atomicAdd(&g_deg_dp_dst[dp_dst[i]], 1);
    }
}

// ---------------- rsqrt(max(deg,1)) ----------------
__global__ void rs_kernel() {
    int i = blockIdx.x * blockDim.x + threadIdx.x;
    if (i < NP) {
        g_rs_pd_src[i] = rsqrtf((float)max(g_deg_pd_src[i], 1));
        g_rs_dp_dst[i] = rsqrtf((float)max(g_deg_dp_dst[i], 1));
    }
    if (i < ND) {
        g_rs_pd_dst[i] = rsqrtf((float)max(g_deg_pd_dst[i], 1));
        g_rs_dp_src[i] = rsqrtf((float)max(g_deg_dp_src[i], 1));
    }
}

// ---------------- two-level exclusive scan ----------------
__global__ void scan_partial(const int* __restrict__ counts, int n, int* __restrict__ bsums) {
    __shared__ int sh[1024];
    int i = blockIdx.x * 1024 + threadIdx.x;
    sh[threadIdx.x] = (i < n) ? counts[i] : 0;
    __syncthreads();
    for (int d = 512; d > 0; d >>= 1) {
        if (threadIdx.x < d) sh[threadIdx.x] += sh[threadIdx.x + d];
        __syncthreads();
    }
    if (threadIdx.x == 0) bsums[blockIdx.x] = sh[0];
}

__global__ void scan_bsums_exclusive(int* __restrict__ a, int n) {
    __shared__ int sh[1024];
    int t = threadIdx.x;
    int v = (t < n) ? a[t] : 0;
    sh[t] = v;
    __syncthreads();
    for (int d = 1; d < 1024; d <<= 1) {
        int add = (t >= d) ? sh[t - d] : 0;
        __syncthreads();
        sh[t] += add;
        __syncthreads();
    }
    if (t < n) a[t] = sh[t] - v;
}

__global__ void scan_write(const int* __restrict__ counts, int n,
                           const int* __restrict__ bsums, int* __restrict__ offsets,
                           int* __restrict__ cursor) {
    __shared__ int sh[1024];
    int i = blockIdx.x * 1024 + threadIdx.x;
    int v = (i < n) ? counts[i] : 0;
    sh[threadIdx.x] = v;
    __syncthreads();
    for (int d = 1; d < 1024; d <<= 1) {
        int add = (threadIdx.x >= d) ? sh[threadIdx.x - d] : 0;
        __syncthreads();
        sh[threadIdx.x] += add;
        __syncthreads();
    }
    int base = bsums[blockIdx.x];
    if (i < n) {
        int off = base + sh[threadIdx.x] - v;
        offsets[i] = off;
        cursor[i]  = off;
    }
    if (i == n - 1) offsets[n] = base + sh[threadIdx.x];
}

// ---------------- CSR scatter (group edges by dst) ----------------
__global__ void scatter_kernel(const int* __restrict__ src, const int* __restrict__ dst,
                               int* __restrict__ cursor, int* __restrict__ csr_idx) {
    int i = blockIdx.x * blockDim.x + threadIdx.x;
    if (i < NE) {
        int p = atomicAdd(&cursor[dst[i]], 1);
        csr_idx[p] = src[i];
    }
}

// ---------------- fused gconv: aggregate + normalize + GEMM + bias + relu ---
__global__ __launch_bounds__(DIM) void gconv_fused(
    const float* __restrict__ x,       // [n_src, DIM]
    const int* __restrict__ off,       // [n_dst+1]
    const int* __restrict__ idx,       // [E] src ids grouped by dst
    const float* __restrict__ rs_src,  // [n_src]
    const float* __restrict__ rs_dst,  // [n_dst]
    const float* __restrict__ W,       // [DIM, DIM] row-major (k, t)
    const float* __restrict__ b,       // [DIM]
    float* __restrict__ out,           // [n_dst, DIM]
    int n_dst) {
    __shared__ float agg[ROWS_PER_BLK][DIM];
    const int t = threadIdx.x;
    const int row0 = blockIdx.x * ROWS_PER_BLK;

    // Phase 1: per-row normalized aggregation (column t handled by thread t)
    #pragma unroll
    for (int r = 0; r < ROWS_PER_BLK; r++) {
        int j = row0 + r;
        float acc = 0.0f;
        if (j < n_dst) {
            int e0 = off[j], e1 = off[j + 1];
            for (int e = e0; e < e1; e++) {
                int s = idx[e];
                acc += __ldg(&rs_src[s]) * __ldg(&x[(size_t)s * DIM + t]);
            }
            acc *= rs_dst[j];
        }
        agg[r][t] = acc;
    }
    __syncthreads();

    // Phase 2: out[j][t] = relu(sum_k agg[j][k] * W[k][t] + b[t]), 8 rows/thread
    float accs[ROWS_PER_BLK];
    float bias = b[t];
    #pragma unroll
    for (int r = 0; r < ROWS_PER_BLK; r++) accs[r] = bias;
    #pragma unroll 4
    for (int k = 0; k < DIM; k++) {
        float w = W[k * DIM + t];
        #pragma unroll
        for (int r = 0; r < ROWS_PER_BLK; r++) accs[r] += agg[r][k] * w;
    }
    #pragma unroll
    for (int r = 0; r < ROWS_PER_BLK; r++) {
        int j = row0 + r;
        if (j < n_dst) out[(size_t)j * DIM + t] = fmaxf(accs[r], 0.0f);
    }
}

// ---------------- host launch ----------------
extern "C" void kernel_launch(void* const* d_in, const int* in_sizes, int n_in,
                              void* d_out, int out_size) {
    const float* h_p    = (const float*)d_in[0];
    const float* h_d    = (const float*)d_in[1];
    const int*   pd_src = (const int*)d_in[2];
    const int*   pd_dst = (const int*)d_in[3];
    const int*   dp_src = (const int*)d_in[4];
    const int*   dp_dst = (const int*)d_in[5];
    const float* W1_pd  = (const float*)d_in[6];
    const float* b1_pd  = (const float*)d_in[7];
    const float* W1_dp  = (const float*)d_in[8];
    const float* b1_dp  = (const float*)d_in[9];
    const float* W2_pd  = (const float*)d_in[10];
    const float* b2_pd  = (const float*)d_in[11];
    const float* W2_dp  = (const float*)d_in[12];
    const float* b2_dp  = (const float*)d_in[13];
    const float* W3_pd  = (const float*)d_in[14];
    const float* b3_pd  = (const float*)d_in[15];
    const float* W3_dp  = (const float*)d_in[16];
    const float* b3_dp  = (const float*)d_in[17];

    float* out_p = (float*)d_out;                       // h_p3 [NP, DIM]
    float* out_d = (float*)d_out + (size_t)NP * DIM;    // h_d3 [ND, DIM]

    // Fetch scratch symbol addresses
    void *p_deg_pd_src, *p_deg_pd_dst, *p_deg_dp_src, *p_deg_dp_dst;
    void *p_rs_pd_src, *p_rs_pd_dst, *p_rs_dp_src, *p_rs_dp_dst;
    void *p_off_pd, *p_off_dp, *p_cur_pd, *p_cur_dp, *p_idx_pd, *p_idx_dp;
    void *p_bsums_pd, *p_bsums_dp, *p_hd1, *p_hd2, *p_hp1, *p_hp2;
    cudaGetSymbolAddress(&p_deg_pd_src, g_deg_pd_src);
    cudaGetSymbolAddress(&p_deg_pd_dst, g_deg_pd_dst);
    cudaGetSymbolAddress(&p_deg_dp_src, g_deg_dp_src);
    cudaGetSymbolAddress(&p_deg_dp_dst, g_deg_dp_dst);
    cudaGetSymbolAddress(&p_rs_pd_src, g_rs_pd_src);
    cudaGetSymbolAddress(&p_rs_pd_dst, g_rs_pd_dst);
    cudaGetSymbolAddress(&p_rs_dp_src, g_rs_dp_src);
    cudaGetSymbolAddress(&p_rs_dp_dst, g_rs_dp_dst);
    cudaGetSymbolAddress(&p_off_pd, g_off_pd);
    cudaGetSymbolAddress(&p_off_dp, g_off_dp);
    cudaGetSymbolAddress(&p_cur_pd, g_cur_pd);
    cudaGetSymbolAddress(&p_cur_dp, g_cur_dp);
    cudaGetSymbolAddress(&p_idx_pd, g_idx_pd);
    cudaGetSymbolAddress(&p_idx_dp, g_idx_dp);
    cudaGetSymbolAddress(&p_bsums_pd, g_bsums_pd);
    cudaGetSymbolAddress(&p_bsums_dp, g_bsums_dp);
    cudaGetSymbolAddress(&p_hd1, g_hd1);
    cudaGetSymbolAddress(&p_hd2, g_hd2);
    cudaGetSymbolAddress(&p_hp1, g_hp1);
    cudaGetSymbolAddress(&p_hp2, g_hp2);

    // 1) zero degree counters
    cudaMemsetAsync(p_deg_pd_src, 0, NP * sizeof(int), 0);
    cudaMemsetAsync(p_deg_pd_dst, 0, ND * sizeof(int), 0);
    cudaMemsetAsync(p_deg_dp_src, 0, ND * sizeof(int), 0);
    cudaMemsetAsync(p_deg_dp_dst, 0, NP * sizeof(int), 0);

    // 2) degree histograms
    hist_kernel<<<(NE + 1023) / 1024, 1024>>>(pd_src, pd_dst, dp_src, dp_dst);

    // 3) rsqrt norms
    rs_kernel<<<(NP + 255) / 256, 256>>>();

    // 4) exclusive scans -> CSR offsets (+ cursor copies)
    {
        int nb_pd = (ND + 1023) / 1024;  // 49
        scan_partial<<<nb_pd, 1024>>>((const int*)p_deg_pd_dst, ND, (int*)p_bsums_pd);
        scan_bsums_exclusive<<<1, 1024>>>((int*)p_bsums_pd, nb_pd);
        scan_write<<<nb_pd, 1024>>>((const int*)p_deg_pd_dst, ND, (const int*)p_bsums_pd,
                                    (int*)p_off_pd, (int*)p_cur_pd);
        int nb_dp = (NP + 1023) / 1024;  // 98
        scan_partial<<<nb_dp, 1024>>>((const int*)p_deg_dp_dst, NP, (int*)p_bsums_dp);
        scan_bsums_exclusive<<<1, 1024>>>((int*)p_bsums_dp, nb_dp);
        scan_write<<<nb_dp, 1024>>>((const int*)p_deg_dp_dst, NP, (const int*)p_bsums_dp,
                                    (int*)p_off_dp, (int*)p_cur_dp);
    }

    // 5) CSR scatter (group edges by destination)
    scatter_kernel<<<(NE + 1023) / 1024, 1024>>>(pd_src, pd_dst, (int*)p_cur_pd, (int*)p_idx_pd);
    scatter_kernel<<<(NE + 1023) / 1024, 1024>>>(dp_src, dp_dst, (int*)p_cur_dp, (int*)p_idx_dp);

    // 6) six fused gconvs
    const int gpd = (ND + ROWS_PER_BLK - 1) / ROWS_PER_BLK;  // dst = d
    const int gdp = (NP + ROWS_PER_BLK - 1) / ROWS_PER_BLK;  // dst = p

    // Layer 1
    gconv_fused<<<gpd, DIM>>>(h_p, (const int*)p_off_pd, (const int*)p_idx_pd,
                              (const float*)p_rs_pd_src, (const float*)p_rs_pd_dst,
                              W1_pd, b1_pd, (float*)p_hd1, ND);
    gconv_fused<<<gdp, DIM>>>(h_d, (const int*)p_off_dp, (const int*)p_idx_dp,
                              (const float*)p_rs_dp_src, (const float*)p_rs_dp_dst,
                              W1_dp, b1_dp, (float*)p_hp1, NP);
    // Layer 2
    gconv_fused<<<gpd, DIM>>>((const float*)p_hp1, (const int*)p_off_pd, (const int*)p_idx_pd,
                              (const float*)p_rs_pd_src, (const float*)p_rs_pd_dst,
                              W2_pd, b2_pd, (float*)p_hd2, ND);
    gconv_fused<<<gdp, DIM>>>((const float*)p_hd1, (const int*)p_off_dp, (const int*)p_idx_dp,
                              (const float*)p_rs_dp_src, (const float*)p_rs_dp_dst,
                              W2_dp, b2_dp, (float*)p_hp2, NP);
    // Layer 3
    gconv_fused<<<gpd, DIM>>>((const float*)p_hp2, (const int*)p_off_pd, (const int*)p_idx_pd,
                              (const float*)p_rs_pd_src, (const float*)p_rs_pd_dst,
                              W3_pd, b3_pd, out_d, ND);
    gconv_fused<<<gdp, DIM>>>((const float*)p_hd2, (const int*)p_off_dp, (const int*)p_idx_dp,
                              (const float*)p_rs_dp_src, (const float*)p_rs_dp_dst,
                              W3_dp, b3_dp, out_p, NP);
}